// round 13
// baseline (speedup 1.0000x reference)
#include <cuda_runtime.h>
#include <cuda_bf16.h>
#include <cstdint>

// ---------------------------------------------------------------------------
// GridPooling, 4-kernel pipeline:
//  K1: keys (byte-hist atomic) + W bf16 hi/lo pack (column-permuted)
//  K2: decoupled-lookback scan (resets hist; rank packed r<<8|count)
//  K3: scatter: singleton -> direct g_sc.z store; multi -> atomic CSR
//  K4: PERSISTENT HMMA GEMM, double-buffered A tiles, B loaded once/CTA,
//      g_sc of next tile prefetched before MMA (hides one DRAM hop)
// ---------------------------------------------------------------------------

#define MAXN     1000000
#define HSIZE    (4 * 128 * 128 * 128)     // 8,388,608 byte cells
#define HWORDS   (HSIZE / 4)
#define NSCANBLK 2048
#define SCAN_T   512
#define PGRID    304                        // 2 CTAs/SM persistent

typedef unsigned long long ull;

__device__ uint32_t g_histb[HWORDS + 2 * NSCANBLK];  // byte hist + lookback state
__device__ int      g_keys[MAXN];
__device__ uint32_t g_rank[HSIZE];         // (rank<<8) | count
__device__ int4     g_sc[MAXN];            // (start, count, first_pid, pad)
__device__ int      g_cursor[MAXN];
__device__ int      g_pidx[MAXN];
__device__ int      g_U[1];
__device__ uint4    g_Bpack4[2304];   // B_hi words [n*36+kp], B_lo at +4608 words

__device__ __forceinline__ int col_perm(int n) {
    int nl = n & 31;
    int t = nl >> 4, r = nl & 3, j = (nl >> 2) & 3;
    return (n & ~31) | (((2 * t + (r >> 1)) << 3) + 2 * j + (r & 1));
}

// ---------------- K1: keys + bpack ----------------

__global__ void keys_bpack_kernel(const int* __restrict__ grid_coord,
                                  const int* __restrict__ batch,
                                  const float* __restrict__ Wg, int N) {
    if (blockIdx.x == gridDim.x - 1) {  // bpack block
        uint32_t* bp = reinterpret_cast<uint32_t*>(g_Bpack4);
        int tid = threadIdx.x;
#pragma unroll
        for (int q = 0; q < 16; q++) {
            int cell = q * 256 + tid;
            int n = cell >> 5;
            int kp = cell & 31;
            float w0 = Wg[(2 * kp) * 128 + n];
            float w1 = Wg[(2 * kp + 1) * 128 + n];
            __nv_bfloat16 h0 = __float2bfloat16(w0), h1 = __float2bfloat16(w1);
            __nv_bfloat16 l0 = __float2bfloat16(w0 - __bfloat162float(h0));
            __nv_bfloat16 l1 = __float2bfloat16(w1 - __bfloat162float(h1));
            int np = col_perm(n);
            bp[np * 36 + kp] =
                ((uint32_t)__bfloat16_as_ushort(h1) << 16) | __bfloat16_as_ushort(h0);
            bp[4608 + np * 36 + kp] =
                ((uint32_t)__bfloat16_as_ushort(l1) << 16) | __bfloat16_as_ushort(l0);
        }
        return;
    }
    int i = blockIdx.x * 256 + threadIdx.x;
    if (i < N) {
        int gx = grid_coord[3 * i + 0] >> 1;
        int gy = grid_coord[3 * i + 1] >> 1;
        int gz = grid_coord[3 * i + 2] >> 1;
        int key = (batch[i] << 21) | (gx << 14) | (gy << 7) | gz;
        g_keys[i] = key;
        atomicAdd(&g_histb[key >> 2], 1u << ((key & 3) * 8));
    }
}

// ---------------- K2: decoupled-lookback scan ----------------

#define FLAGA (1ull << 62)
#define FLAGI (2ull << 62)
#define VMASK ((1ull << 62) - 1)

__device__ __forceinline__ ull warp_reduce_add(ull v) {
#pragma unroll
    for (int off = 16; off; off >>= 1)
        v += __shfl_down_sync(0xffffffffu, v, off);
    return __shfl_sync(0xffffffffu, v, 0);
}

__global__ __launch_bounds__(SCAN_T) void scan_kernel(float* __restrict__ grid_out,
                                                      float* __restrict__ batch_out,
                                                      float* __restrict__ counts_out) {
    __shared__ ull warp_tot[16];
    __shared__ ull sh_prefix;
    int tid = threadIdx.x, bid = blockIdx.x;
    int lane = tid & 31, wid = tid >> 5;

    ull* h8 = reinterpret_cast<ull*>(g_histb);
    ull h = h8[(size_t)bid * SCAN_T + tid];
    h8[(size_t)bid * SCAN_T + tid] = 0ull;   // reset for next replay
    unsigned cbytes[8];
    int occ = 0, cnt = 0;
#pragma unroll
    for (int j = 0; j < 8; j++) {
        unsigned c = (unsigned)(h >> (8 * j)) & 0xFFu;
        cbytes[j] = c;
        occ += (c != 0);
        cnt += c;
    }
    ull v = ((ull)occ << 32) | (unsigned)cnt;

    ull incl = v;
#pragma unroll
    for (int off = 1; off < 32; off <<= 1) {
        ull n = __shfl_up_sync(0xffffffffu, incl, off);
        if (lane >= off) incl += n;
    }
    if (lane == 31) warp_tot[wid] = incl;
    __syncthreads();
    if (wid == 0) {
        ull w = (lane < 16) ? warp_tot[lane] : 0ull;
#pragma unroll
        for (int off = 1; off < 16; off <<= 1) {
            ull n = __shfl_up_sync(0xffffffffu, w, off);
            if (lane >= off) w += n;
        }
        if (lane < 16) warp_tot[lane] = w;
    }
    __syncthreads();
    ull excl_local = ((wid > 0) ? warp_tot[wid - 1] : 0ull) + incl - v;
    ull total = warp_tot[15];

    ull* state = reinterpret_cast<ull*>(g_histb + HWORDS);
    if (tid == 0) {
        if (bid == 0) {
            atomicExch(&state[0], FLAGI | total);
            sh_prefix = 0ull;
        } else {
            atomicExch(&state[bid], FLAGA | total);
        }
    }
    if (bid > 0 && wid == 0) {
        ull excl = 0;
        int idx = bid - 1;
        while (true) {
            int look = idx - lane;
            ull s = (look >= 0) ? atomicAdd(&state[look], 0ull) : FLAGI;
            unsigned f = (unsigned)(s >> 62);
            unsigned incm = __ballot_sync(0xffffffffu, f == 2u);
            unsigned zm = __ballot_sync(0xffffffffu, f == 0u);
            if (incm) {
                int fi = __ffs(incm) - 1;
                unsigned below = (fi == 0) ? 0u : ((1u << fi) - 1u);
                if (zm & below) continue;
                ull contrib = (lane <= fi) ? (s & VMASK) : 0ull;
                excl += warp_reduce_add(contrib);
                break;
            } else {
                if (zm) continue;
                excl += warp_reduce_add(s & VMASK);
                idx -= 32;
            }
        }
        if (lane == 0) {
            atomicExch(&state[bid], FLAGI | (excl + total));
            sh_prefix = excl;
        }
    }
    __syncthreads();
    ull prefix = sh_prefix;
    if (bid == NSCANBLK - 1 && tid == 0)
        g_U[0] = (int)((prefix + total) >> 32);

    int r = (int)((prefix >> 32) + (excl_local >> 32));
    int o = (int)((prefix & 0xFFFFFFFFull) + (excl_local & 0xFFFFFFFFull));
    int key0 = bid * (SCAN_T * 8) + tid * 8;
#pragma unroll
    for (int j = 0; j < 8; j++) {
        unsigned c = cbytes[j];
        if (c) {
            int key = key0 + j;
            g_rank[key] = ((uint32_t)r << 8) | c;
            g_sc[r] = make_int4(o, (int)c, 0, 0);
            g_cursor[r] = o;
            grid_out[3 * r + 0] = (float)((key >> 14) & 127);
            grid_out[3 * r + 1] = (float)((key >> 7) & 127);
            grid_out[3 * r + 2] = (float)(key & 127);
            batch_out[r] = (float)(key >> 21);
            counts_out[r] = (float)c;
            r++;
            o += (int)c;
        }
    }
}

// ---------------- K3: scatter (+ lookback state reset) ----------------

__global__ void scatter_kernel(float* __restrict__ cluster_out, int N) {
    if (blockIdx.x == 0) {
        ull* state = reinterpret_cast<ull*>(g_histb + HWORDS);
        for (int j = threadIdx.x; j < NSCANBLK; j += 256) state[j] = 0ull;
    }
    int i = blockIdx.x * blockDim.x + threadIdx.x;
    if (i < N) {
        uint32_t rc = g_rank[g_keys[i]];
        int r = (int)(rc >> 8);
        if ((rc & 255u) == 1u) {
            g_sc[r].z = i;
        } else {
            int pos = atomicAdd(&g_cursor[r], 1);
            g_pidx[pos] = i;
        }
        cluster_out[i] = (float)r;
    }
}

// ---------------- K4: persistent HMMA GEMM ----------------
// smem words: A0 hi 0 / lo 4608; A1 hi 9216 / lo 13824; B hi 18432 / lo 23040

#define GEMM_SMEM 110592

__device__ __forceinline__ void mma_bf16(float* c, const uint32_t* a,
                                         uint32_t b0, uint32_t b1) {
    asm volatile(
        "mma.sync.aligned.m16n8k16.row.col.f32.bf16.bf16.f32 "
        "{%0,%1,%2,%3}, {%4,%5,%6,%7}, {%8,%9}, {%0,%1,%2,%3};"
        : "+f"(c[0]), "+f"(c[1]), "+f"(c[2]), "+f"(c[3])
        : "r"(a[0]), "r"(a[1]), "r"(a[2]), "r"(a[3]), "r"(b0), "r"(b1));
}

__device__ __forceinline__ void ldsm4(uint32_t* r, uint32_t addr) {
    asm volatile(
        "ldmatrix.sync.aligned.m8n8.x4.shared.b16 {%0,%1,%2,%3}, [%4];"
        : "=r"(r[0]), "=r"(r[1]), "=r"(r[2]), "=r"(r[3]) : "r"(addr));
}

__device__ __forceinline__ uint32_t smem_u32(const void* p) {
    uint32_t a;
    asm("{ .reg .u64 t; cvta.to.shared.u64 t, %1; cvt.u32.u64 %0, t; }"
        : "=r"(a) : "l"(p));
    return a;
}

__device__ __forceinline__ uint32_t pack_bf16(float x0, float x1) {
    __nv_bfloat16 b0 = __float2bfloat16(x0), b1 = __float2bfloat16(x1);
    return ((uint32_t)__bfloat16_as_ushort(b1) << 16) | __bfloat16_as_ushort(b0);
}

// gather tile tt with its sc already in hand -> STS into A[tbuf]; coord means
// and padded-row defaults for this tile's rows.
__device__ __forceinline__ void gather_tile(
    int tt, uint32_t* sm, int tbuf, int row, int quarter, int4 sc,
    const float* __restrict__ feat, const float* __restrict__ coord,
    float* __restrict__ counts_out, float* __restrict__ coord_out,
    float* __restrict__ grid_out, float* __restrict__ batch_out,
    int U, int N) {
    int rb = tt << 7;
    int gr = rb + row;
    float acc[16];
#pragma unroll
    for (int q = 0; q < 16; q++) acc[q] = 0.f;
    float cx = 0.f, cy = 0.f, cz = 0.f;
    float inv = 0.f;
    if (gr < U) {
        int s = sc.x, c = sc.y;
        inv = 1.0f / (float)c;
        int p = (c == 1) ? sc.z : g_pidx[s];
        for (int j = 0; j < c; j++) {
            int pn = (j + 1 < c) ? g_pidx[s + j + 1] : 0;
            const float4* f =
                reinterpret_cast<const float4*>(feat + (size_t)p * 64 + quarter * 16);
            if (quarter == 0) {
                cx += coord[3 * p + 0];
                cy += coord[3 * p + 1];
                cz += coord[3 * p + 2];
            }
#pragma unroll
            for (int q = 0; q < 4; q++) {
                float4 vv = f[q];
                acc[4 * q + 0] += vv.x;
                acc[4 * q + 1] += vv.y;
                acc[4 * q + 2] += vv.z;
                acc[4 * q + 3] += vv.w;
            }
            p = pn;
        }
    }
    int wb = tbuf * 9216 + row * 36 + quarter * 8;
    uint4 hi0, hi1, lo0, lo1;
    uint32_t* hw = reinterpret_cast<uint32_t*>(&hi0);
    uint32_t* lw = reinterpret_cast<uint32_t*>(&lo0);
#pragma unroll
    for (int c2 = 0; c2 < 8; c2++) {
        float x0 = acc[2 * c2] * inv, x1 = acc[2 * c2 + 1] * inv;
        __nv_bfloat16 h0 = __float2bfloat16(x0), h1 = __float2bfloat16(x1);
        float r0 = x0 - __bfloat162float(h0);
        float r1 = x1 - __bfloat162float(h1);
        uint32_t hp = ((uint32_t)__bfloat16_as_ushort(h1) << 16) |
                      __bfloat16_as_ushort(h0);
        uint32_t lp = pack_bf16(r0, r1);
        if (c2 < 4) { hw[c2] = hp; lw[c2] = lp; }
        else { reinterpret_cast<uint32_t*>(&hi1)[c2 - 4] = hp;
               reinterpret_cast<uint32_t*>(&lo1)[c2 - 4] = lp; }
    }
    *reinterpret_cast<uint4*>(sm + wb) = hi0;
    *reinterpret_cast<uint4*>(sm + wb + 4) = hi1;
    *reinterpret_cast<uint4*>(sm + 4608 + wb) = lo0;
    *reinterpret_cast<uint4*>(sm + 4608 + wb + 4) = lo1;

    if (quarter == 0 && gr < N) {
        if (gr < U) {
            coord_out[3 * gr + 0] = cx * inv;
            coord_out[3 * gr + 1] = cy * inv;
            coord_out[3 * gr + 2] = cz * inv;
        } else {
            batch_out[gr] = -1.0f;
            grid_out[3 * gr + 0] = 127.0f;
            grid_out[3 * gr + 1] = 127.0f;
            grid_out[3 * gr + 2] = 127.0f;
            counts_out[gr] = 0.0f;
            coord_out[3 * gr + 0] = 0.0f;
            coord_out[3 * gr + 1] = 0.0f;
            coord_out[3 * gr + 2] = 0.0f;
        }
    }
}

__global__ __launch_bounds__(512, 2) void gemm_kernel(
    const float* __restrict__ bias, const float* __restrict__ feat,
    const float* __restrict__ coord,
    float* __restrict__ counts_out, float* __restrict__ coord_out,
    float* __restrict__ grid_out, float* __restrict__ batch_out,
    float* __restrict__ out, int N) {
    extern __shared__ uint32_t sm[];
    int tid = threadIdx.x;
    int U = g_U[0];
    int T = (N + 127) >> 7;
    int stride = gridDim.x;

    // B tiles: once per CTA
    {
        uint4* dst = reinterpret_cast<uint4*>(sm + 18432);
#pragma unroll
        for (int q = 0; q < 5; q++) {
            int idx = q * 512 + tid;
            if (idx < 2304) dst[idx] = g_Bpack4[idx];
        }
    }

    int wid = tid >> 5, lane = tid & 31;
    int g = lane >> 2, tig = lane & 3;
    int wm = wid & 3, wn = wid >> 2;
    int lrow = lane & 15, khalf = lane >> 4;
    uint32_t smb = smem_u32(sm);
    uint32_t aOff = 4u * ((wm * 32 + lrow) * 36 + khalf * 4);
    uint32_t bAddr = smb + 73728u + 4u * ((wn * 32 + lrow) * 36 + khalf * 4);
    int row = tid >> 2, quarter = tid & 3;

    // loop-invariant bias fragment
    float4 bv[2];
#pragma unroll
    for (int p = 0; p < 2; p++)
        bv[p] = *reinterpret_cast<const float4*>(bias + wn * 32 + 16 * p + 4 * tig);

    int t = blockIdx.x;
    int buf = 0;
    bool first = true;

    while (t < T) {
        int rb = t << 7;
        bool real = rb < U;
        if (first) {
            if (real) {
                int4 sc0 = make_int4(0, 1, 0, 0);
                if (rb + row < U) sc0 = g_sc[rb + row];
                gather_tile(t, sm, buf, row, quarter, sc0, feat, coord,
                            counts_out, coord_out, grid_out, batch_out, U, N);
            }
            __syncthreads();
            first = false;
        }

        int tn = t + stride;
        bool gn = (tn < T) && ((tn << 7) < U);

        // prefetch next tile's sc BEFORE the MMA (latency hides under MMA)
        int4 sc_n = make_int4(0, 1, 0, 0);
        if (gn) {
            int gr_n = (tn << 7) + row;
            if (gr_n < U) sc_n = g_sc[gr_n];
        }

        if (real) {
            // MMA on A[buf]
            uint32_t aAddr = smb + (buf ? 36864u : 0u) + aOff;
            float c[2][4][4];
#pragma unroll
            for (int mt = 0; mt < 2; mt++)
#pragma unroll
                for (int nt = 0; nt < 4; nt++)
#pragma unroll
                    for (int q = 0; q < 4; q++) c[mt][nt][q] = 0.f;

#pragma unroll
            for (int ks = 0; ks < 4; ks++) {
                uint32_t off = ks * 32u;
                uint32_t ah0[4], ah1[4], al0[4], al1[4];
                ldsm4(ah0, aAddr + off);
                ldsm4(ah1, aAddr + 2304u + off);
                ldsm4(al0, aAddr + 18432u + off);
                ldsm4(al1, aAddr + 18432u + 2304u + off);
                uint32_t bh0[4], bh1[4], bl0[4], bl1[4];
                ldsm4(bh0, bAddr + off);
                ldsm4(bh1, bAddr + 2304u + off);
                ldsm4(bl0, bAddr + 18432u + off);
                ldsm4(bl1, bAddr + 18432u + 2304u + off);
#pragma unroll
                for (int nt = 0; nt < 4; nt++) {
                    uint32_t b0h = (nt < 2 ? bh0 : bh1)[nt & 1];
                    uint32_t b1h = (nt < 2 ? bh0 : bh1)[2 + (nt & 1)];
                    mma_bf16(c[0][nt], ah0, b0h, b1h);
                    mma_bf16(c[1][nt], ah1, b0h, b1h);
                    mma_bf16(c[0][nt], al0, b0h, b1h);
                    mma_bf16(c[1][nt], al1, b0h, b1h);
                    uint32_t b0l = (nt < 2 ? bl0 : bl1)[nt & 1];
                    uint32_t b1l = (nt < 2 ? bl0 : bl1)[2 + (nt & 1)];
                    mma_bf16(c[0][nt], ah0, b0l, b1l);
                    mma_bf16(c[1][nt], ah1, b0l, b1l);
                }
            }

            // epilogue
#pragma unroll
            for (int mt = 0; mt < 2; mt++) {
#pragma unroll
                for (int half = 0; half < 2; half++) {
                    int gr = rb + wm * 32 + mt * 16 + g + half * 8;
                    if (gr >= N) continue;
                    bool on = gr < U;
#pragma unroll
                    for (int p = 0; p < 2; p++) {
                        int col = wn * 32 + 16 * p + 4 * tig;
                        float4 v;
                        if (on) {
                            v.x = c[mt][2 * p][half * 2 + 0] + bv[p].x;
                            v.y = c[mt][2 * p][half * 2 + 1] + bv[p].y;
                            v.z = c[mt][2 * p + 1][half * 2 + 0] + bv[p].z;
                            v.w = c[mt][2 * p + 1][half * 2 + 1] + bv[p].w;
                        } else {
                            v = make_float4(0.f, 0.f, 0.f, 0.f);
                        }
                        *reinterpret_cast<float4*>(out + (size_t)gr * 128 + col) = v;
                    }
                }
            }
        } else {
            // pure padding tile: zero feat rows + defaults
#pragma unroll
            for (int q = 0; q < 4; q++) {
                int p2 = q * 512 + tid;
                int rowz = rb + (p2 >> 4);
                if (rowz < N)
                    reinterpret_cast<float4*>(out + (size_t)rowz * 128)[p2 & 15] =
                        make_float4(0.f, 0.f, 0.f, 0.f);
            }
            if (tid < 128) {
                int gr = rb + tid;
                if (gr < N) {
                    batch_out[gr] = -1.0f;
                    grid_out[3 * gr + 0] = 127.0f;
                    grid_out[3 * gr + 1] = 127.0f;
                    grid_out[3 * gr + 2] = 127.0f;
                    counts_out[gr] = 0.0f;
                    coord_out[3 * gr + 0] = 0.0f;
                    coord_out[3 * gr + 1] = 0.0f;
                    coord_out[3 * gr + 2] = 0.0f;
                }
            }
        }

        if (gn)
            gather_tile(tn, sm, buf ^ 1, row, quarter, sc_n, feat, coord,
                        counts_out, coord_out, grid_out, batch_out, U, N);

        __syncthreads();
        buf ^= 1;
        t = tn;
    }
}

// ---------------- launch ----------------

extern "C" void kernel_launch(void* const* d_in, const int* in_sizes, int n_in,
                              void* d_out, int out_size) {
    const float* feat       = (const float*)d_in[0];
    const float* coord      = (const float*)d_in[1];
    const int*   grid_coord = (const int*)d_in[2];
    const int*   batch      = (const int*)d_in[3];
    const float* W          = (const float*)d_in[4];
    const float* bias       = (const float*)d_in[5];
    int N = in_sizes[3];
    if (N > MAXN) N = MAXN;

    float* out         = (float*)d_out;
    float* feat_out    = out;
    float* coord_out   = out + (size_t)N * 128;
    float* grid_out    = coord_out + (size_t)N * 3;
    float* batch_out   = grid_out + (size_t)N * 3;
    float* cluster_out = batch_out + N;
    float* counts_out  = cluster_out + N;

    int nb = (N + 255) / 256;
    keys_bpack_kernel<<<nb + 1, 256>>>(grid_coord, batch, W, N);
    scan_kernel<<<NSCANBLK, SCAN_T>>>(grid_out, batch_out, counts_out);
    scatter_kernel<<<nb, 256>>>(cluster_out, N);

    static int smem_set = 0;
    if (!smem_set) {
        cudaFuncSetAttribute(gemm_kernel,
                             cudaFuncAttributeMaxDynamicSharedMemorySize,
                             GEMM_SMEM);
        smem_set = 1;
    }
    gemm_kernel<<<PGRID, 512, GEMM_SMEM>>>(
        bias, feat, coord, counts_out, coord_out, grid_out, batch_out,
        feat_out, N);
}

// round 14
// speedup vs baseline: 1.0624x; 1.0624x over previous
#include <cuda_runtime.h>
#include <cuda_bf16.h>
#include <cstdint>

// ---------------------------------------------------------------------------
// GridPooling, 4-kernel pipeline:
//  K1: keys (byte-hist atomic) + W bf16 hi/lo pack (column-permuted)
//  K2: decoupled-lookback scan (resets hist; rank packed r<<8|count)
//  K3: scatter: singleton -> direct g_sc.z store; multi -> atomic CSR
//  K4: PERSISTENT HMMA GEMM, double-buffered A tiles, B loaded once/CTA,
//      next tile's (start,count) staged through SMEM scratch before the MMA
//      (LDG->STS liveness only; no registers held across the MMA block)
// ---------------------------------------------------------------------------

#define MAXN     1000000
#define HSIZE    (4 * 128 * 128 * 128)     // 8,388,608 byte cells
#define HWORDS   (HSIZE / 4)
#define NSCANBLK 2048
#define SCAN_T   512
#define PGRID    304                        // 2 CTAs/SM persistent

typedef unsigned long long ull;

__device__ uint32_t g_histb[HWORDS + 2 * NSCANBLK];  // byte hist + lookback state
__device__ int      g_keys[MAXN];
__device__ uint32_t g_rank[HSIZE];         // (rank<<8) | count
__device__ int4     g_sc[MAXN];            // (start, count, first_pid, pad)
__device__ int      g_cursor[MAXN];
__device__ int      g_pidx[MAXN];
__device__ int      g_U[1];
__device__ uint4    g_Bpack4[2304];   // B_hi words [n*36+kp], B_lo at +4608 words

__device__ __forceinline__ int col_perm(int n) {
    int nl = n & 31;
    int t = nl >> 4, r = nl & 3, j = (nl >> 2) & 3;
    return (n & ~31) | (((2 * t + (r >> 1)) << 3) + 2 * j + (r & 1));
}

// ---------------- K1: keys + bpack ----------------

__global__ void keys_bpack_kernel(const int* __restrict__ grid_coord,
                                  const int* __restrict__ batch,
                                  const float* __restrict__ Wg, int N) {
    if (blockIdx.x == gridDim.x - 1) {  // bpack block
        uint32_t* bp = reinterpret_cast<uint32_t*>(g_Bpack4);
        int tid = threadIdx.x;
#pragma unroll
        for (int q = 0; q < 16; q++) {
            int cell = q * 256 + tid;
            int n = cell >> 5;
            int kp = cell & 31;
            float w0 = Wg[(2 * kp) * 128 + n];
            float w1 = Wg[(2 * kp + 1) * 128 + n];
            __nv_bfloat16 h0 = __float2bfloat16(w0), h1 = __float2bfloat16(w1);
            __nv_bfloat16 l0 = __float2bfloat16(w0 - __bfloat162float(h0));
            __nv_bfloat16 l1 = __float2bfloat16(w1 - __bfloat162float(h1));
            int np = col_perm(n);
            bp[np * 36 + kp] =
                ((uint32_t)__bfloat16_as_ushort(h1) << 16) | __bfloat16_as_ushort(h0);
            bp[4608 + np * 36 + kp] =
                ((uint32_t)__bfloat16_as_ushort(l1) << 16) | __bfloat16_as_ushort(l0);
        }
        return;
    }
    int i = blockIdx.x * 256 + threadIdx.x;
    if (i < N) {
        int gx = grid_coord[3 * i + 0] >> 1;
        int gy = grid_coord[3 * i + 1] >> 1;
        int gz = grid_coord[3 * i + 2] >> 1;
        int key = (batch[i] << 21) | (gx << 14) | (gy << 7) | gz;
        g_keys[i] = key;
        atomicAdd(&g_histb[key >> 2], 1u << ((key & 3) * 8));
    }
}

// ---------------- K2: decoupled-lookback scan ----------------

#define FLAGA (1ull << 62)
#define FLAGI (2ull << 62)
#define VMASK ((1ull << 62) - 1)

__device__ __forceinline__ ull warp_reduce_add(ull v) {
#pragma unroll
    for (int off = 16; off; off >>= 1)
        v += __shfl_down_sync(0xffffffffu, v, off);
    return __shfl_sync(0xffffffffu, v, 0);
}

__global__ __launch_bounds__(SCAN_T) void scan_kernel(float* __restrict__ grid_out,
                                                      float* __restrict__ batch_out,
                                                      float* __restrict__ counts_out) {
    __shared__ ull warp_tot[16];
    __shared__ ull sh_prefix;
    int tid = threadIdx.x, bid = blockIdx.x;
    int lane = tid & 31, wid = tid >> 5;

    ull* h8 = reinterpret_cast<ull*>(g_histb);
    ull h = h8[(size_t)bid * SCAN_T + tid];
    h8[(size_t)bid * SCAN_T + tid] = 0ull;   // reset for next replay
    unsigned cbytes[8];
    int occ = 0, cnt = 0;
#pragma unroll
    for (int j = 0; j < 8; j++) {
        unsigned c = (unsigned)(h >> (8 * j)) & 0xFFu;
        cbytes[j] = c;
        occ += (c != 0);
        cnt += c;
    }
    ull v = ((ull)occ << 32) | (unsigned)cnt;

    ull incl = v;
#pragma unroll
    for (int off = 1; off < 32; off <<= 1) {
        ull n = __shfl_up_sync(0xffffffffu, incl, off);
        if (lane >= off) incl += n;
    }
    if (lane == 31) warp_tot[wid] = incl;
    __syncthreads();
    if (wid == 0) {
        ull w = (lane < 16) ? warp_tot[lane] : 0ull;
#pragma unroll
        for (int off = 1; off < 16; off <<= 1) {
            ull n = __shfl_up_sync(0xffffffffu, w, off);
            if (lane >= off) w += n;
        }
        if (lane < 16) warp_tot[lane] = w;
    }
    __syncthreads();
    ull excl_local = ((wid > 0) ? warp_tot[wid - 1] : 0ull) + incl - v;
    ull total = warp_tot[15];

    ull* state = reinterpret_cast<ull*>(g_histb + HWORDS);
    if (tid == 0) {
        if (bid == 0) {
            atomicExch(&state[0], FLAGI | total);
            sh_prefix = 0ull;
        } else {
            atomicExch(&state[bid], FLAGA | total);
        }
    }
    if (bid > 0 && wid == 0) {
        ull excl = 0;
        int idx = bid - 1;
        while (true) {
            int look = idx - lane;
            ull s = (look >= 0) ? atomicAdd(&state[look], 0ull) : FLAGI;
            unsigned f = (unsigned)(s >> 62);
            unsigned incm = __ballot_sync(0xffffffffu, f == 2u);
            unsigned zm = __ballot_sync(0xffffffffu, f == 0u);
            if (incm) {
                int fi = __ffs(incm) - 1;
                unsigned below = (fi == 0) ? 0u : ((1u << fi) - 1u);
                if (zm & below) continue;
                ull contrib = (lane <= fi) ? (s & VMASK) : 0ull;
                excl += warp_reduce_add(contrib);
                break;
            } else {
                if (zm) continue;
                excl += warp_reduce_add(s & VMASK);
                idx -= 32;
            }
        }
        if (lane == 0) {
            atomicExch(&state[bid], FLAGI | (excl + total));
            sh_prefix = excl;
        }
    }
    __syncthreads();
    ull prefix = sh_prefix;
    if (bid == NSCANBLK - 1 && tid == 0)
        g_U[0] = (int)((prefix + total) >> 32);

    int r = (int)((prefix >> 32) + (excl_local >> 32));
    int o = (int)((prefix & 0xFFFFFFFFull) + (excl_local & 0xFFFFFFFFull));
    int key0 = bid * (SCAN_T * 8) + tid * 8;
#pragma unroll
    for (int j = 0; j < 8; j++) {
        unsigned c = cbytes[j];
        if (c) {
            int key = key0 + j;
            g_rank[key] = ((uint32_t)r << 8) | c;
            g_sc[r] = make_int4(o, (int)c, 0, 0);
            g_cursor[r] = o;
            grid_out[3 * r + 0] = (float)((key >> 14) & 127);
            grid_out[3 * r + 1] = (float)((key >> 7) & 127);
            grid_out[3 * r + 2] = (float)(key & 127);
            batch_out[r] = (float)(key >> 21);
            counts_out[r] = (float)c;
            r++;
            o += (int)c;
        }
    }
}

// ---------------- K3: scatter (+ lookback state reset) ----------------

__global__ void scatter_kernel(float* __restrict__ cluster_out, int N) {
    if (blockIdx.x == 0) {
        ull* state = reinterpret_cast<ull*>(g_histb + HWORDS);
        for (int j = threadIdx.x; j < NSCANBLK; j += 256) state[j] = 0ull;
    }
    int i = blockIdx.x * blockDim.x + threadIdx.x;
    if (i < N) {
        uint32_t rc = g_rank[g_keys[i]];
        int r = (int)(rc >> 8);
        if ((rc & 255u) == 1u) {
            g_sc[r].z = i;
        } else {
            int pos = atomicAdd(&g_cursor[r], 1);
            g_pidx[pos] = i;
        }
        cluster_out[i] = (float)r;
    }
}

// ---------------- K4: persistent HMMA GEMM ----------------
// smem words: A0 hi 0 / lo 4608; A1 hi 9216 / lo 13824; B hi 18432 / lo 23040;
// sc scratch (uint2/thread) at 27648..28672.  Total 28672 words = 114688 B.

#define GEMM_SMEM 114688
#define SC_SCRATCH 27648

__device__ __forceinline__ void mma_bf16(float* c, const uint32_t* a,
                                         uint32_t b0, uint32_t b1) {
    asm volatile(
        "mma.sync.aligned.m16n8k16.row.col.f32.bf16.bf16.f32 "
        "{%0,%1,%2,%3}, {%4,%5,%6,%7}, {%8,%9}, {%0,%1,%2,%3};"
        : "+f"(c[0]), "+f"(c[1]), "+f"(c[2]), "+f"(c[3])
        : "r"(a[0]), "r"(a[1]), "r"(a[2]), "r"(a[3]), "r"(b0), "r"(b1));
}

__device__ __forceinline__ void ldsm4(uint32_t* r, uint32_t addr) {
    asm volatile(
        "ldmatrix.sync.aligned.m8n8.x4.shared.b16 {%0,%1,%2,%3}, [%4];"
        : "=r"(r[0]), "=r"(r[1]), "=r"(r[2]), "=r"(r[3]) : "r"(addr));
}

__device__ __forceinline__ uint32_t smem_u32(const void* p) {
    uint32_t a;
    asm("{ .reg .u64 t; cvta.to.shared.u64 t, %1; cvt.u32.u64 %0, t; }"
        : "=r"(a) : "l"(p));
    return a;
}

__device__ __forceinline__ uint32_t pack_bf16(float x0, float x1) {
    __nv_bfloat16 b0 = __float2bfloat16(x0), b1 = __float2bfloat16(x1);
    return ((uint32_t)__bfloat16_as_ushort(b1) << 16) | __bfloat16_as_ushort(b0);
}

// stage (p_or_start, count) for tile tt into this thread's scratch slot.
// Singleton resolved at store time. Short LDG->STS liveness.
__device__ __forceinline__ void stage_sc(int tt, uint32_t* sm, int tid,
                                         int row, int U) {
    int gr = (tt << 7) + row;
    uint2 pk = make_uint2(0u, 0u);
    if (gr < U) {
        int4 s4 = g_sc[gr];
        pk.x = (s4.y == 1) ? (uint32_t)s4.z : (uint32_t)s4.x;
        pk.y = (uint32_t)s4.y;
    }
    *reinterpret_cast<uint2*>(sm + SC_SCRATCH + tid * 2) = pk;
}

// gather tile tt using the staged scratch -> STS into A[tbuf]; coord means
// and padded-row defaults for this tile's rows.
__device__ __forceinline__ void gather_tile(
    int tt, uint32_t* sm, int tbuf, int tid, int row, int quarter,
    const float* __restrict__ feat, const float* __restrict__ coord,
    float* __restrict__ counts_out, float* __restrict__ coord_out,
    float* __restrict__ grid_out, float* __restrict__ batch_out,
    int U, int N) {
    int rb = tt << 7;
    int gr = rb + row;
    float acc[16];
#pragma unroll
    for (int q = 0; q < 16; q++) acc[q] = 0.f;
    float cx = 0.f, cy = 0.f, cz = 0.f;
    float inv = 0.f;
    if (gr < U) {
        uint2 pk = *reinterpret_cast<uint2*>(sm + SC_SCRATCH + tid * 2);
        int c = (int)pk.y;
        int s = (int)pk.x;          // point id if c==1, else CSR start
        inv = 1.0f / (float)c;
        int p = (c == 1) ? s : g_pidx[s];
        for (int j = 0; j < c; j++) {
            int pn = (j + 1 < c) ? g_pidx[s + j + 1] : 0;
            const float4* f =
                reinterpret_cast<const float4*>(feat + (size_t)p * 64 + quarter * 16);
            if (quarter == 0) {
                cx += coord[3 * p + 0];
                cy += coord[3 * p + 1];
                cz += coord[3 * p + 2];
            }
#pragma unroll
            for (int q = 0; q < 4; q++) {
                float4 vv = f[q];
                acc[4 * q + 0] += vv.x;
                acc[4 * q + 1] += vv.y;
                acc[4 * q + 2] += vv.z;
                acc[4 * q + 3] += vv.w;
            }
            p = pn;
        }
    }
    int wb = tbuf * 9216 + row * 36 + quarter * 8;
    uint4 hi0, hi1, lo0, lo1;
    uint32_t* hw = reinterpret_cast<uint32_t*>(&hi0);
    uint32_t* lw = reinterpret_cast<uint32_t*>(&lo0);
#pragma unroll
    for (int c2 = 0; c2 < 8; c2++) {
        float x0 = acc[2 * c2] * inv, x1 = acc[2 * c2 + 1] * inv;
        __nv_bfloat16 h0 = __float2bfloat16(x0), h1 = __float2bfloat16(x1);
        float r0 = x0 - __bfloat162float(h0);
        float r1 = x1 - __bfloat162float(h1);
        uint32_t hp = ((uint32_t)__bfloat16_as_ushort(h1) << 16) |
                      __bfloat16_as_ushort(h0);
        uint32_t lp = pack_bf16(r0, r1);
        if (c2 < 4) { hw[c2] = hp; lw[c2] = lp; }
        else { reinterpret_cast<uint32_t*>(&hi1)[c2 - 4] = hp;
               reinterpret_cast<uint32_t*>(&lo1)[c2 - 4] = lp; }
    }
    *reinterpret_cast<uint4*>(sm + wb) = hi0;
    *reinterpret_cast<uint4*>(sm + wb + 4) = hi1;
    *reinterpret_cast<uint4*>(sm + 4608 + wb) = lo0;
    *reinterpret_cast<uint4*>(sm + 4608 + wb + 4) = lo1;

    if (quarter == 0 && gr < N) {
        if (gr < U) {
            coord_out[3 * gr + 0] = cx * inv;
            coord_out[3 * gr + 1] = cy * inv;
            coord_out[3 * gr + 2] = cz * inv;
        } else {
            batch_out[gr] = -1.0f;
            grid_out[3 * gr + 0] = 127.0f;
            grid_out[3 * gr + 1] = 127.0f;
            grid_out[3 * gr + 2] = 127.0f;
            counts_out[gr] = 0.0f;
            coord_out[3 * gr + 0] = 0.0f;
            coord_out[3 * gr + 1] = 0.0f;
            coord_out[3 * gr + 2] = 0.0f;
        }
    }
}

__global__ __launch_bounds__(512, 2) void gemm_kernel(
    const float* __restrict__ bias, const float* __restrict__ feat,
    const float* __restrict__ coord,
    float* __restrict__ counts_out, float* __restrict__ coord_out,
    float* __restrict__ grid_out, float* __restrict__ batch_out,
    float* __restrict__ out, int N) {
    extern __shared__ uint32_t sm[];
    int tid = threadIdx.x;
    int U = g_U[0];
    int T = (N + 127) >> 7;
    int stride = gridDim.x;

    // B tiles: once per CTA
    {
        uint4* dst = reinterpret_cast<uint4*>(sm + 18432);
#pragma unroll
        for (int q = 0; q < 5; q++) {
            int idx = q * 512 + tid;
            if (idx < 2304) dst[idx] = g_Bpack4[idx];
        }
    }

    int wid = tid >> 5, lane = tid & 31;
    int g = lane >> 2, tig = lane & 3;
    int wm = wid & 3, wn = wid >> 2;
    int lrow = lane & 15, khalf = lane >> 4;
    uint32_t smb = smem_u32(sm);
    uint32_t aOff = 4u * ((wm * 32 + lrow) * 36 + khalf * 4);
    uint32_t bAddr = smb + 73728u + 4u * ((wn * 32 + lrow) * 36 + khalf * 4);
    int row = tid >> 2, quarter = tid & 3;

    // loop-invariant bias fragment
    float4 bv[2];
#pragma unroll
    for (int p = 0; p < 2; p++)
        bv[p] = *reinterpret_cast<const float4*>(bias + wn * 32 + 16 * p + 4 * tig);

    int t = blockIdx.x;
    int buf = 0;
    bool first = true;

    while (t < T) {
        int rb = t << 7;
        bool real = rb < U;
        if (first) {
            if (real) {
                stage_sc(t, sm, tid, row, U);
                gather_tile(t, sm, buf, tid, row, quarter, feat, coord,
                            counts_out, coord_out, grid_out, batch_out, U, N);
            }
            __syncthreads();
            first = false;
        }

        int tn = t + stride;
        bool gn = (tn < T) && ((tn << 7) < U);

        // stage next tile's sc into thread-private scratch BEFORE the MMA;
        // LDG latency hides under the MMA, registers freed at the STS.
        if (gn) stage_sc(tn, sm, tid, row, U);

        if (real) {
            // MMA on A[buf]
            uint32_t aAddr = smb + (buf ? 36864u : 0u) + aOff;
            float c[2][4][4];
#pragma unroll
            for (int mt = 0; mt < 2; mt++)
#pragma unroll
                for (int nt = 0; nt < 4; nt++)
#pragma unroll
                    for (int q = 0; q < 4; q++) c[mt][nt][q] = 0.f;

#pragma unroll
            for (int ks = 0; ks < 4; ks++) {
                uint32_t off = ks * 32u;
                uint32_t ah0[4], ah1[4], al0[4], al1[4];
                ldsm4(ah0, aAddr + off);
                ldsm4(ah1, aAddr + 2304u + off);
                ldsm4(al0, aAddr + 18432u + off);
                ldsm4(al1, aAddr + 18432u + 2304u + off);
                uint32_t bh0[4], bh1[4], bl0[4], bl1[4];
                ldsm4(bh0, bAddr + off);
                ldsm4(bh1, bAddr + 2304u + off);
                ldsm4(bl0, bAddr + 18432u + off);
                ldsm4(bl1, bAddr + 18432u + 2304u + off);
#pragma unroll
                for (int nt = 0; nt < 4; nt++) {
                    uint32_t b0h = (nt < 2 ? bh0 : bh1)[nt & 1];
                    uint32_t b1h = (nt < 2 ? bh0 : bh1)[2 + (nt & 1)];
                    mma_bf16(c[0][nt], ah0, b0h, b1h);
                    mma_bf16(c[1][nt], ah1, b0h, b1h);
                    mma_bf16(c[0][nt], al0, b0h, b1h);
                    mma_bf16(c[1][nt], al1, b0h, b1h);
                    uint32_t b0l = (nt < 2 ? bl0 : bl1)[nt & 1];
                    uint32_t b1l = (nt < 2 ? bl0 : bl1)[2 + (nt & 1)];
                    mma_bf16(c[0][nt], ah0, b0l, b1l);
                    mma_bf16(c[1][nt], ah1, b0l, b1l);
                }
            }

            // epilogue
#pragma unroll
            for (int mt = 0; mt < 2; mt++) {
#pragma unroll
                for (int half = 0; half < 2; half++) {
                    int gr = rb + wm * 32 + mt * 16 + g + half * 8;
                    if (gr >= N) continue;
                    bool on = gr < U;
#pragma unroll
                    for (int p = 0; p < 2; p++) {
                        int col = wn * 32 + 16 * p + 4 * tig;
                        float4 v;
                        if (on) {
                            v.x = c[mt][2 * p][half * 2 + 0] + bv[p].x;
                            v.y = c[mt][2 * p][half * 2 + 1] + bv[p].y;
                            v.z = c[mt][2 * p + 1][half * 2 + 0] + bv[p].z;
                            v.w = c[mt][2 * p + 1][half * 2 + 1] + bv[p].w;
                        } else {
                            v = make_float4(0.f, 0.f, 0.f, 0.f);
                        }
                        *reinterpret_cast<float4*>(out + (size_t)gr * 128 + col) = v;
                    }
                }
            }
        } else {
            // pure padding tile: zero feat rows + defaults
#pragma unroll
            for (int q = 0; q < 4; q++) {
                int p2 = q * 512 + tid;
                int rowz = rb + (p2 >> 4);
                if (rowz < N)
                    reinterpret_cast<float4*>(out + (size_t)rowz * 128)[p2 & 15] =
                        make_float4(0.f, 0.f, 0.f, 0.f);
            }
            if (tid < 128) {
                int gr = rb + tid;
                if (gr < N) {
                    batch_out[gr] = -1.0f;
                    grid_out[3 * gr + 0] = 127.0f;
                    grid_out[3 * gr + 1] = 127.0f;
                    grid_out[3 * gr + 2] = 127.0f;
                    counts_out[gr] = 0.0f;
                    coord_out[3 * gr + 0] = 0.0f;
                    coord_out[3 * gr + 1] = 0.0f;
                    coord_out[3 * gr + 2] = 0.0f;
                }
            }
        }

        if (gn)
            gather_tile(tn, sm, buf ^ 1, tid, row, quarter, feat, coord,
                        counts_out, coord_out, grid_out, batch_out, U, N);

        __syncthreads();
        buf ^= 1;
        t = tn;
    }
}

// ---------------- launch ----------------

extern "C" void kernel_launch(void* const* d_in, const int* in_sizes, int n_in,
                              void* d_out, int out_size) {
    const float* feat       = (const float*)d_in[0];
    const float* coord      = (const float*)d_in[1];
    const int*   grid_coord = (const int*)d_in[2];
    const int*   batch      = (const int*)d_in[3];
    const float* W          = (const float*)d_in[4];
    const float* bias       = (const float*)d_in[5];
    int N = in_sizes[3];
    if (N > MAXN) N = MAXN;

    float* out         = (float*)d_out;
    float* feat_out    = out;
    float* coord_out   = out + (size_t)N * 128;
    float* grid_out    = coord_out + (size_t)N * 3;
    float* batch_out   = grid_out + (size_t)N * 3;
    float* cluster_out = batch_out + N;
    float* counts_out  = cluster_out + N;

    int nb = (N + 255) / 256;
    keys_bpack_kernel<<<nb + 1, 256>>>(grid_coord, batch, W, N);
    scan_kernel<<<NSCANBLK, SCAN_T>>>(grid_out, batch_out, counts_out);
    scatter_kernel<<<nb, 256>>>(cluster_out, N);

    static int smem_set = 0;
    if (!smem_set) {
        cudaFuncSetAttribute(gemm_kernel,
                             cudaFuncAttributeMaxDynamicSharedMemorySize,
                             GEMM_SMEM);
        smem_set = 1;
    }
    gemm_kernel<<<PGRID, 512, GEMM_SMEM>>>(
        bias, feat, coord, counts_out, coord_out, grid_out, batch_out,
        feat_out, N);
}